// round 2
// baseline (speedup 1.0000x reference)
#include <cuda_runtime.h>
#include <cstdint>

// Problem constants
#define NB    4
#define NS    4096
#define NDIN  2048
#define NDOUT 2048
#define NR    16
#define NE    12
#define NM    (NB * NS)          // 16384 rows total

// GEMM tiling
#define BM 128
#define BN 128
#define BK 16
#define LDS_S (BM + 4)           // 132: padded smem stride, keeps 16B alignment

// Scratch (allocation-free rule: __device__ globals)
__device__ __align__(16) float g_lx[NM * NR];            // 1 MB
__device__ __align__(16) float g_comb[NB * NDOUT * NR];  // 512 KB

// ---------------------------------------------------------------------------
// Kernel 1: combined[b,o,r] = sum_e gate[b,e] * W_up[e,o,r]   (SCALE folded =1)
// ---------------------------------------------------------------------------
__global__ void k_combine(const float* __restrict__ gate,
                          const float* __restrict__ W_up) {
    int idx = blockIdx.x * 256 + threadIdx.x;       // over NB*NDOUT*NR
    if (idx >= NB * NDOUT * NR) return;
    int b   = idx / (NDOUT * NR);
    int orr = idx - b * (NDOUT * NR);
    float s = 0.f;
#pragma unroll
    for (int e = 0; e < NE; e++)
        s += __ldg(&gate[b * NE + e]) * __ldg(&W_up[(size_t)e * NDOUT * NR + orr]);
    g_comb[idx] = s;  // MULTIPLIER*SCALE == 1.0
}

// ---------------------------------------------------------------------------
// Kernel 2: lx[m,r] = sum_i x[m,i] * W_down[r,i]
// One block per row m; x row staged in smem, 16-thread groups per r.
// ---------------------------------------------------------------------------
__global__ void k_lx(const float* __restrict__ x,
                     const float* __restrict__ W_down) {
    __shared__ float sx[NDIN];
    int m = blockIdx.x;
    const float* xr = x + (size_t)m * NDIN;
    for (int i = threadIdx.x; i < NDIN; i += 256) sx[i] = xr[i];
    __syncthreads();

    int r = threadIdx.x >> 4, lane = threadIdx.x & 15;
    const float* wr = W_down + (size_t)r * NDIN;
    float s = 0.f;
    for (int i = lane; i < NDIN; i += 16) s += sx[i] * wr[i];
#pragma unroll
    for (int off = 8; off; off >>= 1)
        s += __shfl_down_sync(0xffffffffu, s, off, 16);
    if (lane == 0) g_lx[m * NR + r] = s;
}

// ---------------------------------------------------------------------------
// Main GEMM: out[m,n] = sum_k x[m,k]*W[n,k]  (+ LoRA via extra virtual K-tile)
// 128x128 tile, BK=16, 256 threads, 8x8 per thread, double-buffered smem,
// packed fma.rn.f32x2 accumulation (B300: FFMA2 is 2x scalar FFMA tput).
// ---------------------------------------------------------------------------
__device__ __forceinline__ unsigned long long dupf(float v) {
    unsigned long long d;
    asm("mov.b64 %0, {%1, %1};" : "=l"(d) : "f"(v));
    return d;
}
__device__ __forceinline__ void ffma2(unsigned long long& c,
                                      unsigned long long a,
                                      unsigned long long b) {
    asm("fma.rn.f32x2 %0, %1, %2, %0;" : "+l"(c) : "l"(a), "l"(b));
}

__device__ __forceinline__ void mma16(const float (*As_)[LDS_S],
                                      const float (*Bs_)[LDS_S],
                                      int ty, int tx,
                                      unsigned long long acc[8][4]) {
#pragma unroll
    for (int kk = 0; kk < BK; kk++) {
        float4 a0 = *(const float4*)&As_[kk][ty * 8];
        float4 a1 = *(const float4*)&As_[kk][ty * 8 + 4];
        ulonglong2 bb0 = *(const ulonglong2*)&Bs_[kk][tx * 8];
        ulonglong2 bb1 = *(const ulonglong2*)&Bs_[kk][tx * 8 + 4];
        unsigned long long a2[8];
        a2[0] = dupf(a0.x); a2[1] = dupf(a0.y); a2[2] = dupf(a0.z); a2[3] = dupf(a0.w);
        a2[4] = dupf(a1.x); a2[5] = dupf(a1.y); a2[6] = dupf(a1.z); a2[7] = dupf(a1.w);
        unsigned long long b2[4] = {bb0.x, bb0.y, bb1.x, bb1.y};
#pragma unroll
        for (int i = 0; i < 8; i++) {
            ffma2(acc[i][0], a2[i], b2[0]);
            ffma2(acc[i][1], a2[i], b2[1]);
            ffma2(acc[i][2], a2[i], b2[2]);
            ffma2(acc[i][3], a2[i], b2[3]);
        }
    }
}

__global__ void __launch_bounds__(256, 2)
k_gemm(const float* __restrict__ x, const float* __restrict__ W,
       float* __restrict__ out) {
    __shared__ float As[2][BK][LDS_S];
    __shared__ float Bs[2][BK][LDS_S];

    const int tid = threadIdx.x;
    const int tx = tid & 15;   // n
    const int ty = tid >> 4;   // m
    const int rowBase = blockIdx.y * BM;
    const int colBase = blockIdx.x * BN;
    const int b = rowBase / NS;   // BM=128 divides NS=4096 -> one batch per block

    const float* Ap = x + (size_t)rowBase * NDIN;
    const float* Bp = W + (size_t)colBase * NDIN;

    // loader indices: each thread loads 2x float4 per matrix per tile
    const int lr = tid >> 2;        // 0..63
    const int lc = (tid & 3) * 4;   // 0,4,8,12

    unsigned long long acc[8][4];
#pragma unroll
    for (int i = 0; i < 8; i++)
#pragma unroll
        for (int j = 0; j < 4; j++) acc[i][j] = 0ull;

    float4 ra[2], rb[2];
    // prologue: tile 0 -> buffer 0 (transposed: smem is [k][m])
#pragma unroll
    for (int it = 0; it < 2; it++) {
        ra[it] = *(const float4*)(Ap + (size_t)(lr + 64 * it) * NDIN + lc);
        rb[it] = *(const float4*)(Bp + (size_t)(lr + 64 * it) * NDIN + lc);
    }
#pragma unroll
    for (int it = 0; it < 2; it++) {
        int rr = lr + 64 * it;
        As[0][lc + 0][rr] = ra[it].x; As[0][lc + 1][rr] = ra[it].y;
        As[0][lc + 2][rr] = ra[it].z; As[0][lc + 3][rr] = ra[it].w;
        Bs[0][lc + 0][rr] = rb[it].x; Bs[0][lc + 1][rr] = rb[it].y;
        Bs[0][lc + 2][rr] = rb[it].z; Bs[0][lc + 3][rr] = rb[it].w;
    }

    const int NT = NDIN / BK;  // 128
    for (int kt = 0; kt < NT; kt++) {
        const int cur = kt & 1;
        if (kt + 1 < NT) {
            const float* An = Ap + (kt + 1) * BK;
            const float* Bn = Bp + (kt + 1) * BK;
#pragma unroll
            for (int it = 0; it < 2; it++) {
                ra[it] = *(const float4*)(An + (size_t)(lr + 64 * it) * NDIN + lc);
                rb[it] = *(const float4*)(Bn + (size_t)(lr + 64 * it) * NDIN + lc);
            }
        }
        __syncthreads();   // buffer `cur` writes visible; everyone done reading `nxt`
        mma16(As[cur], Bs[cur], ty, tx, acc);
        if (kt + 1 < NT) {
            const int nxt = (kt + 1) & 1;
#pragma unroll
            for (int it = 0; it < 2; it++) {
                int rr = lr + 64 * it;
                As[nxt][lc + 0][rr] = ra[it].x; As[nxt][lc + 1][rr] = ra[it].y;
                As[nxt][lc + 2][rr] = ra[it].z; As[nxt][lc + 3][rr] = ra[it].w;
                Bs[nxt][lc + 0][rr] = rb[it].x; Bs[nxt][lc + 1][rr] = rb[it].y;
                Bs[nxt][lc + 2][rr] = rb[it].z; Bs[nxt][lc + 3][rr] = rb[it].w;
            }
        }
    }

    // LoRA epilogue as one extra virtual K-tile (K=R=16):
    // A-epi = lx[rowBase.., 0..15] (ld=16), B-epi = comb[b, colBase.., 0..15] (ld=16)
    {
        const float* lxp = g_lx + (size_t)rowBase * NR;
        const float* cbp = g_comb + ((size_t)b * NDOUT + colBase) * NR;
#pragma unroll
        for (int it = 0; it < 2; it++) {
            int rr = lr + 64 * it;
            float4 va = *(const float4*)(lxp + (size_t)rr * NR + lc);
            float4 vb = *(const float4*)(cbp + (size_t)rr * NR + lc);
            As[0][lc + 0][rr] = va.x; As[0][lc + 1][rr] = va.y;
            As[0][lc + 2][rr] = va.z; As[0][lc + 3][rr] = va.w;
            Bs[0][lc + 0][rr] = vb.x; Bs[0][lc + 1][rr] = vb.y;
            Bs[0][lc + 2][rr] = vb.z; Bs[0][lc + 3][rr] = vb.w;
        }
        __syncthreads();
        mma16(As[0], Bs[0], ty, tx, acc);
    }

    // Write C: 8 rows x 8 cols per thread, 2x STG.128 per row
    union U { unsigned long long u; float2 f; };
    float* Cp = out + (size_t)rowBase * NDOUT + colBase;
#pragma unroll
    for (int i = 0; i < 8; i++) {
        U u0, u1, u2, u3;
        u0.u = acc[i][0]; u1.u = acc[i][1]; u2.u = acc[i][2]; u3.u = acc[i][3];
        float4 v0 = make_float4(u0.f.x, u0.f.y, u1.f.x, u1.f.y);
        float4 v1 = make_float4(u2.f.x, u2.f.y, u3.f.x, u3.f.y);
        float* rowp = Cp + (size_t)(ty * 8 + i) * NDOUT + tx * 8;
        *(float4*)(rowp)     = v0;
        *(float4*)(rowp + 4) = v1;
    }
}

// ---------------------------------------------------------------------------
// Launch: metadata order = x, gate, W_org, W_down, W_up ; output fp32
// ---------------------------------------------------------------------------
extern "C" void kernel_launch(void* const* d_in, const int* in_sizes, int n_in,
                              void* d_out, int out_size) {
    const float* x      = (const float*)d_in[0];
    const float* gate   = (const float*)d_in[1];
    const float* W_org  = (const float*)d_in[2];
    const float* W_down = (const float*)d_in[3];
    const float* W_up   = (const float*)d_in[4];
    float* out = (float*)d_out;

    k_combine<<<(NB * NDOUT * NR + 255) / 256, 256>>>(gate, W_up);
    k_lx<<<NM, 256>>>(x, W_down);
    dim3 grid(NDOUT / BN, NM / BM);   // (16, 128) = 2048 CTAs
    k_gemm<<<grid, 256>>>(x, W_org, out);
}

// round 4
// speedup vs baseline: 2.0014x; 2.0014x over previous
#include <cuda_runtime.h>
#include <cuda_bf16.h>
#include <cstdint>

// ---------------- problem constants ----------------
#define NB 4
#define NS 4096
#define NDIN 2048
#define NDOUT 2048
#define NR 16
#define NE 12
#define NM (NB * NS)  // 16384

// ---------------- GEMM tiling ----------------
#define BM 256
#define BN 128
#define CK 32                    // K per chunk (bf16)
#define NCHUNK (NDIN / CK)       // 64
#define NCHTOT (NCHUNK + 1)      // +1 virtual LoRA chunk (K=16, zero padded to 32)
#define NSTAGE 3

#define ROWB 80                  // padded smem row stride in bytes (conflict-free ldmatrix)
#define A_PART (BM * ROWB)       // 20480
#define B_PART (BN * ROWB)       // 10240
#define OF_B (2 * A_PART)        // 40960
#define STAGE_SZ (2 * A_PART + 2 * B_PART)  // 61440
#define SMEM_TOTAL (NSTAGE * STAGE_SZ)      // 184320

// ---------------- scratch (device globals: allocation-free rule) ----------------
__device__ __align__(16) __nv_bfloat16 g_xh[(size_t)NM * NDIN];
__device__ __align__(16) __nv_bfloat16 g_xl[(size_t)NM * NDIN];
__device__ __align__(16) __nv_bfloat16 g_wh[(size_t)NDOUT * NDIN];
__device__ __align__(16) __nv_bfloat16 g_wl[(size_t)NDOUT * NDIN];
__device__ __align__(16) __nv_bfloat16 g_lxh[(size_t)NM * 32];        // [m][32], cols16+ = 0
__device__ __align__(16) __nv_bfloat16 g_lxl[(size_t)NM * 32];
__device__ __align__(16) __nv_bfloat16 g_cbh[(size_t)NB * NDOUT * 32];
__device__ __align__(16) __nv_bfloat16 g_cbl[(size_t)NB * NDOUT * 32];

// ---------------- PTX helpers (all plain sm_80+ instructions) ----------------
__device__ __forceinline__ uint32_t smem_u32(const void* p) {
    uint32_t a;
    asm("{ .reg .u64 t; cvta.to.shared.u64 t, %1; cvt.u32.u64 %0, t; }" : "=r"(a) : "l"(p));
    return a;
}
__device__ __forceinline__ void cp16(uint32_t saddr, const void* gptr) {
    asm volatile("cp.async.cg.shared.global [%0], [%1], 16;"
                 :: "r"(saddr), "l"(__cvta_generic_to_global(gptr)) : "memory");
}
__device__ __forceinline__ void cp_commit() {
    asm volatile("cp.async.commit_group;" ::: "memory");
}
__device__ __forceinline__ void cp_wait2() {
    asm volatile("cp.async.wait_group 2;" ::: "memory");
}
#define LDSM4(r0, r1, r2, r3, addr)                                           \
    asm volatile("ldmatrix.sync.aligned.m8n8.x4.shared.b16 {%0,%1,%2,%3}, [%4];" \
                 : "=r"(r0), "=r"(r1), "=r"(r2), "=r"(r3) : "r"(addr))
#define MMA16816(c, a, b0, b1)                                                \
    asm volatile("mma.sync.aligned.m16n8k16.row.col.f32.bf16.bf16.f32 "       \
                 "{%0,%1,%2,%3},{%4,%5,%6,%7},{%8,%9},{%0,%1,%2,%3};"         \
                 : "+f"((c)[0]), "+f"((c)[1]), "+f"((c)[2]), "+f"((c)[3])     \
                 : "r"((a)[0]), "r"((a)[1]), "r"((a)[2]), "r"((a)[3]),        \
                   "r"(b0), "r"(b1))

// ---------------- pre-kernels ----------------
union BF8 { __nv_bfloat16 b[8]; uint4 u; };

__device__ __forceinline__ void split8(const float* src, __nv_bfloat16* hi,
                                       __nv_bfloat16* lo, size_t i) {
    float f[8];
    float4 v0 = *(const float4*)(src + i);
    float4 v1 = *(const float4*)(src + i + 4);
    f[0]=v0.x; f[1]=v0.y; f[2]=v0.z; f[3]=v0.w;
    f[4]=v1.x; f[5]=v1.y; f[6]=v1.z; f[7]=v1.w;
    BF8 h, l;
#pragma unroll
    for (int j = 0; j < 8; j++) {
        h.b[j] = __float2bfloat16(f[j]);
        l.b[j] = __float2bfloat16(f[j] - __bfloat162float(h.b[j]));
    }
    *(uint4*)(hi + i) = h.u;
    *(uint4*)(lo + i) = l.u;
}
__global__ void k_split_x(const float* __restrict__ x) {
    size_t i = ((size_t)blockIdx.x * 256 + threadIdx.x) * 8;
    split8(x, g_xh, g_xl, i);
}
__global__ void k_split_w(const float* __restrict__ w) {
    size_t i = ((size_t)blockIdx.x * 256 + threadIdx.x) * 8;
    split8(w, g_wh, g_wl, i);
}

// combined[b,o,r] = sum_e gate[b,e]*W_up[e,o,r]; write bf16 hi/lo padded [b*NDOUT+o][32]
__global__ void k_combine(const float* __restrict__ gate,
                          const float* __restrict__ W_up) {
    int idx = blockIdx.x * 256 + threadIdx.x;
    if (idx >= NB * NDOUT * NR) return;
    int b = idx / (NDOUT * NR);
    int orr = idx - b * (NDOUT * NR);
    int o = orr >> 4, r = orr & 15;
    float s = 0.f;
#pragma unroll
    for (int e = 0; e < NE; e++)
        s += __ldg(&gate[b * NE + e]) * __ldg(&W_up[(size_t)e * NDOUT * NR + orr]);
    size_t off = ((size_t)b * NDOUT + o) * 32;
    __nv_bfloat16 h = __float2bfloat16(s);
    g_cbh[off + r] = h;
    g_cbl[off + r] = __float2bfloat16(s - __bfloat162float(h));
    g_cbh[off + 16 + r] = __float2bfloat16(0.f);
    g_cbl[off + 16 + r] = __float2bfloat16(0.f);
}

// lx[m,r] = sum_k x[m,k]*W_down[r,k]; write bf16 hi/lo padded [m][32]
__global__ void k_lx(const float* __restrict__ x, const float* __restrict__ Wd) {
    __shared__ float sx[128][65];
    __shared__ float swd[16][65];
    int t = threadIdx.x;
    int r = t & 15, mg = t >> 4;
    int rowBase = blockIdx.x * 128;
    float acc[8] = {0, 0, 0, 0, 0, 0, 0, 0};
    for (int kc = 0; kc < NDIN; kc += 64) {
#pragma unroll
        for (int j = 0; j < 8; j++) {
            int gid = t + 256 * j;
            int row = gid >> 4, c4 = (gid & 15) * 4;
            float4 v = *(const float4*)(x + (size_t)(rowBase + row) * NDIN + kc + c4);
            sx[row][c4 + 0] = v.x; sx[row][c4 + 1] = v.y;
            sx[row][c4 + 2] = v.z; sx[row][c4 + 3] = v.w;
        }
        {
            int wrow = t >> 4, c4 = (t & 15) * 4;
            float4 v = *(const float4*)(Wd + (size_t)wrow * NDIN + kc + c4);
            swd[wrow][c4 + 0] = v.x; swd[wrow][c4 + 1] = v.y;
            swd[wrow][c4 + 2] = v.z; swd[wrow][c4 + 3] = v.w;
        }
        __syncthreads();
#pragma unroll 4
        for (int k = 0; k < 64; k++) {
            float w = swd[r][k];
#pragma unroll
            for (int i = 0; i < 8; i++) acc[i] += sx[mg * 8 + i][k] * w;
        }
        __syncthreads();
    }
#pragma unroll
    for (int i = 0; i < 8; i++) {
        int m = rowBase + mg * 8 + i;
        __nv_bfloat16 h = __float2bfloat16(acc[i]);
        g_lxh[(size_t)m * 32 + r] = h;
        g_lxl[(size_t)m * 32 + r] = __float2bfloat16(acc[i] - __bfloat162float(h));
        g_lxh[(size_t)m * 32 + 16 + r] = __float2bfloat16(0.f);
        g_lxl[(size_t)m * 32 + 16 + r] = __float2bfloat16(0.f);
    }
}

// ---------------- main GEMM: mma.sync bf16 3-split ----------------
__device__ __forceinline__ void issue_chunk(uint32_t sb0, int stage, int idx,
                                            int rowBase, int colBase, int b, int tid) {
    const __nv_bfloat16 *ah, *al, *bh, *bl;
    int sA, sB;
    if (idx < NCHUNK) {
        size_t ko = (size_t)idx * CK;
        ah = g_xh + (size_t)rowBase * NDIN + ko;
        al = g_xl + (size_t)rowBase * NDIN + ko;
        bh = g_wh + (size_t)colBase * NDIN + ko;
        bl = g_wl + (size_t)colBase * NDIN + ko;
        sA = NDIN; sB = NDIN;
    } else {  // LoRA virtual chunk
        ah = g_lxh + (size_t)rowBase * 32;
        al = g_lxl + (size_t)rowBase * 32;
        bh = g_cbh + ((size_t)b * NDOUT + colBase) * 32;
        bl = g_cbl + ((size_t)b * NDOUT + colBase) * 32;
        sA = 32; sB = 32;
    }
    uint32_t s = sb0 + stage * STAGE_SZ;
    // A: 256 rows x 4 x 16B, hi and lo (2 transfers each per thread)
#pragma unroll
    for (int j = 0; j < 2; j++) {
        int id = tid + 512 * j;
        int row = id >> 2, c = id & 3;
        uint32_t so = row * ROWB + c * 16;
        cp16(s + so, ah + (size_t)row * sA + c * 8);
        cp16(s + A_PART + so, al + (size_t)row * sA + c * 8);
    }
    // B: 128 rows x 4 x 16B, hi and lo (1 transfer each per thread)
    {
        int row = tid >> 2, c = tid & 3;
        uint32_t so = OF_B + row * ROWB + c * 16;
        cp16(s + so, bh + (size_t)row * sB + c * 8);
        cp16(s + B_PART + so, bl + (size_t)row * sB + c * 8);
    }
}

__global__ void __launch_bounds__(512, 1) k_gemm(float* __restrict__ out) {
    extern __shared__ char smem[];
    uint32_t sb0 = smem_u32(smem);
    const int tid = threadIdx.x;
    const int wid = tid >> 5, lane = tid & 31;
    const int wm = wid >> 2, wn = wid & 3;      // 4x4 warp grid, warp tile 64x32
    const int rowBase = blockIdx.y * BM;
    const int colBase = blockIdx.x * BN;
    const int b = blockIdx.y >> 4;              // 4096/256 = 16 row-blocks per batch

    float acc[4][4][4];
#pragma unroll
    for (int i = 0; i < 4; i++)
#pragma unroll
        for (int j = 0; j < 4; j++)
#pragma unroll
            for (int q = 0; q < 4; q++) acc[i][j][q] = 0.f;

    issue_chunk(sb0, 0, 0, rowBase, colBase, b, tid); cp_commit();
    issue_chunk(sb0, 1, 1, rowBase, colBase, b, tid); cp_commit();

    const int lr = lane & 15, lc = lane >> 4;

    for (int kc = 0; kc < NCHTOT; kc++) {
        if (kc + 2 < NCHTOT)
            issue_chunk(sb0, (kc + 2) % NSTAGE, kc + 2, rowBase, colBase, b, tid);
        cp_commit();
        cp_wait2();
        __syncthreads();

        const uint32_t Ab = sb0 + (kc % NSTAGE) * STAGE_SZ;
        const uint32_t Bb = Ab + OF_B;
#pragma unroll
        for (int ks = 0; ks < 2; ks++) {
            const int koff = ks * 32 + lc * 16;
            // B fragments: 4 n-tiles (2x ldmatrix.x4 over 16 n-rows), hi and lo
            uint32_t bh[4][2], bl[4][2];
#pragma unroll
            for (int bp = 0; bp < 2; bp++) {
                uint32_t addr = Bb + (wn * 32 + bp * 16 + lr) * ROWB + koff;
                uint32_t r0, r1, r2, r3;
                LDSM4(r0, r1, r2, r3, addr);
                bh[bp * 2 + 0][0] = r0; bh[bp * 2 + 0][1] = r2;
                bh[bp * 2 + 1][0] = r1; bh[bp * 2 + 1][1] = r3;
                LDSM4(r0, r1, r2, r3, addr + B_PART);
                bl[bp * 2 + 0][0] = r0; bl[bp * 2 + 0][1] = r2;
                bl[bp * 2 + 1][0] = r1; bl[bp * 2 + 1][1] = r3;
            }
#pragma unroll
            for (int mt = 0; mt < 4; mt++) {
                uint32_t a_h[4], a_l[4];
                uint32_t addr = Ab + (wm * 64 + mt * 16 + lr) * ROWB + koff;
                LDSM4(a_h[0], a_h[1], a_h[2], a_h[3], addr);
                LDSM4(a_l[0], a_l[1], a_l[2], a_l[3], addr + A_PART);
#pragma unroll
                for (int nt = 0; nt < 4; nt++) {
                    MMA16816(acc[mt][nt], a_h, bh[nt][0], bh[nt][1]);
                    MMA16816(acc[mt][nt], a_h, bl[nt][0], bl[nt][1]);
                    MMA16816(acc[mt][nt], a_l, bh[nt][0], bh[nt][1]);
                }
            }
        }
        __syncthreads();
    }

    // ---------------- epilogue: write fp32 ----------------
#pragma unroll
    for (int mt = 0; mt < 4; mt++) {
#pragma unroll
        for (int nt = 0; nt < 4; nt++) {
            int row = rowBase + wm * 64 + mt * 16 + (lane >> 2);
            int col = colBase + wn * 32 + nt * 8 + (lane & 3) * 2;
            float2 v0 = make_float2(acc[mt][nt][0], acc[mt][nt][1]);
            float2 v1 = make_float2(acc[mt][nt][2], acc[mt][nt][3]);
            *(float2*)&out[(size_t)row * NDOUT + col] = v0;
            *(float2*)&out[(size_t)(row + 8) * NDOUT + col] = v1;
        }
    }
}

// ---------------- launch ----------------
extern "C" void kernel_launch(void* const* d_in, const int* in_sizes, int n_in,
                              void* d_out, int out_size) {
    const float* x      = (const float*)d_in[0];
    const float* gate   = (const float*)d_in[1];
    const float* W_org  = (const float*)d_in[2];
    const float* W_down = (const float*)d_in[3];
    const float* W_up   = (const float*)d_in[4];
    float* out = (float*)d_out;

    cudaFuncSetAttribute(k_gemm, cudaFuncAttributeMaxDynamicSharedMemorySize, SMEM_TOTAL);

    k_split_x<<<(size_t)NM * NDIN / 2048, 256>>>(x);
    k_split_w<<<(size_t)NDOUT * NDIN / 2048, 256>>>(W_org);
    k_combine<<<(NB * NDOUT * NR + 255) / 256, 256>>>(gate, W_up);
    k_lx<<<NM / 128, 256>>>(x, W_down);

    dim3 grid(NDOUT / BN, NM / BM);   // (16, 64) = 1024 CTAs
    k_gemm<<<grid, 512, SMEM_TOTAL>>>(out);
}

// round 5
// speedup vs baseline: 2.2640x; 1.1312x over previous
#include <cuda_runtime.h>
#include <cuda_bf16.h>
#include <cstdint>

// ---------------- problem constants ----------------
#define NB 4
#define NS 4096
#define NDIN 2048
#define NDOUT 2048
#define NR 16
#define NE 12
#define NM (NB * NS)  // 16384

// ---------------- GEMM tiling ----------------
#define BM 128
#define BN 256
#define CK 32                    // K per chunk (bf16): 64B rows
#define NCHUNK (NDIN / CK)       // 64
#define NCHTOT (NCHUNK + 1)      // +1 virtual LoRA chunk
#define NSTAGE 4

#define A_SZ (BM * 64)                       // 8192
#define B_SZ (BN * 64)                       // 16384
#define OF_AL A_SZ
#define OF_BH (2 * A_SZ)
#define OF_BL (2 * A_SZ + B_SZ)
#define STAGE_SZ (2 * A_SZ + 2 * B_SZ)       // 49152
#define SMEM_TOTAL (NSTAGE * STAGE_SZ)       // 196608

// ---------------- scratch (device globals: allocation-free rule) ----------------
__device__ __align__(16) __nv_bfloat16 g_xh[(size_t)NM * NDIN];
__device__ __align__(16) __nv_bfloat16 g_xl[(size_t)NM * NDIN];
__device__ __align__(16) __nv_bfloat16 g_wh[(size_t)NDOUT * NDIN];
__device__ __align__(16) __nv_bfloat16 g_wl[(size_t)NDOUT * NDIN];
__device__ __align__(16) __nv_bfloat16 g_lxh[(size_t)NM * 32];        // [m][32], cols16+ = 0
__device__ __align__(16) __nv_bfloat16 g_lxl[(size_t)NM * 32];
__device__ __align__(16) __nv_bfloat16 g_cbh[(size_t)NB * NDOUT * 32];
__device__ __align__(16) __nv_bfloat16 g_cbl[(size_t)NB * NDOUT * 32];

// ---------------- PTX helpers (plain sm_80+ instructions only) ----------------
__device__ __forceinline__ uint32_t smem_u32(const void* p) {
    uint32_t a;
    asm("{ .reg .u64 t; cvta.to.shared.u64 t, %1; cvt.u32.u64 %0, t; }" : "=r"(a) : "l"(p));
    return a;
}
__device__ __forceinline__ void cp16(uint32_t saddr, const void* gptr) {
    asm volatile("cp.async.cg.shared.global [%0], [%1], 16;"
                 :: "r"(saddr), "l"(__cvta_generic_to_global(gptr)) : "memory");
}
__device__ __forceinline__ void cp_commit() {
    asm volatile("cp.async.commit_group;" ::: "memory");
}
__device__ __forceinline__ void cp_wait3() {
    asm volatile("cp.async.wait_group 3;" ::: "memory");
}
#define LDSM4(r0, r1, r2, r3, addr)                                              \
    asm volatile("ldmatrix.sync.aligned.m8n8.x4.shared.b16 {%0,%1,%2,%3}, [%4];" \
                 : "=r"(r0), "=r"(r1), "=r"(r2), "=r"(r3) : "r"(addr))
#define MMA16816(c, a, b0, b1)                                                \
    asm volatile("mma.sync.aligned.m16n8k16.row.col.f32.bf16.bf16.f32 "       \
                 "{%0,%1,%2,%3},{%4,%5,%6,%7},{%8,%9},{%0,%1,%2,%3};"         \
                 : "+f"((c)[0]), "+f"((c)[1]), "+f"((c)[2]), "+f"((c)[3])     \
                 : "r"((a)[0]), "r"((a)[1]), "r"((a)[2]), "r"((a)[3]),        \
                   "r"(b0), "r"(b1))

// 64B-row swizzle: 16B-chunk' = chunk ^ ((row>>1)&3). Conflict-free for
// 8-row ldmatrix phases AND 8-lane STS.128 phases (all 8 16B-groups hit).
__device__ __forceinline__ uint32_t swof(int row, int ch) {
    return (uint32_t)(row * 64 + ((ch ^ ((row >> 1) & 3)) << 4));
}

// ---------------- pre-kernels ----------------
union BF8 { __nv_bfloat16 b[8]; uint4 u; };

__device__ __forceinline__ void split8(const float* src, __nv_bfloat16* hi,
                                       __nv_bfloat16* lo, size_t i) {
    float f[8];
    float4 v0 = *(const float4*)(src + i);
    float4 v1 = *(const float4*)(src + i + 4);
    f[0]=v0.x; f[1]=v0.y; f[2]=v0.z; f[3]=v0.w;
    f[4]=v1.x; f[5]=v1.y; f[6]=v1.z; f[7]=v1.w;
    BF8 h, l;
#pragma unroll
    for (int j = 0; j < 8; j++) {
        h.b[j] = __float2bfloat16(f[j]);
        l.b[j] = __float2bfloat16(f[j] - __bfloat162float(h.b[j]));
    }
    *(uint4*)(hi + i) = h.u;
    *(uint4*)(lo + i) = l.u;
}
__global__ void k_split_x(const float* __restrict__ x) {
    size_t i = ((size_t)blockIdx.x * 256 + threadIdx.x) * 8;
    split8(x, g_xh, g_xl, i);
}
__global__ void k_split_w(const float* __restrict__ w) {
    size_t i = ((size_t)blockIdx.x * 256 + threadIdx.x) * 8;
    split8(w, g_wh, g_wl, i);
}

// combined[b,o,r] = sum_e gate[b,e]*W_up[e,o,r]; bf16 hi/lo padded [b*NDOUT+o][32]
__global__ void k_combine(const float* __restrict__ gate,
                          const float* __restrict__ W_up) {
    int idx = blockIdx.x * 256 + threadIdx.x;
    if (idx >= NB * NDOUT * NR) return;
    int b = idx / (NDOUT * NR);
    int orr = idx - b * (NDOUT * NR);
    int o = orr >> 4, r = orr & 15;
    float s = 0.f;
#pragma unroll
    for (int e = 0; e < NE; e++)
        s += __ldg(&gate[b * NE + e]) * __ldg(&W_up[(size_t)e * NDOUT * NR + orr]);
    size_t off = ((size_t)b * NDOUT + o) * 32;
    __nv_bfloat16 h = __float2bfloat16(s);
    g_cbh[off + r] = h;
    g_cbl[off + r] = __float2bfloat16(s - __bfloat162float(h));
    g_cbh[off + 16 + r] = __float2bfloat16(0.f);
    g_cbl[off + 16 + r] = __float2bfloat16(0.f);
}

// lx[m,r] = sum_k x[m,k]*W_down[r,k]; 512 blocks x 32 rows, 512 threads
__global__ void __launch_bounds__(512) k_lx(const float* __restrict__ x,
                                            const float* __restrict__ Wd) {
    __shared__ float4 sx[32][33];   // 32 rows x 128 k (fp32), padded
    __shared__ float4 swd[16][33];
    const int t = threadIdx.x;
    const int m = t >> 4, r = t & 15;
    const int rowBase = blockIdx.x * 32;
    float acc = 0.f;
    for (int kc = 0; kc < NDIN; kc += 128) {
#pragma unroll
        for (int j = 0; j < 2; j++) {
            int id = t + 512 * j;
            int row = id >> 5, c4 = id & 31;
            sx[row][c4] = *(const float4*)(x + (size_t)(rowBase + row) * NDIN + kc + c4 * 4);
        }
        {
            int row = t >> 5, c4 = t & 31;
            swd[row][c4] = *(const float4*)(Wd + (size_t)row * NDIN + kc + c4 * 4);
        }
        __syncthreads();
#pragma unroll 8
        for (int k4 = 0; k4 < 32; k4++) {
            float4 a = sx[m][k4], w = swd[r][k4];
            acc += a.x * w.x + a.y * w.y + a.z * w.z + a.w * w.w;
        }
        __syncthreads();
    }
    int mm = rowBase + m;
    __nv_bfloat16 h = __float2bfloat16(acc);
    g_lxh[(size_t)mm * 32 + r] = h;
    g_lxl[(size_t)mm * 32 + r] = __float2bfloat16(acc - __bfloat162float(h));
    g_lxh[(size_t)mm * 32 + 16 + r] = __float2bfloat16(0.f);
    g_lxl[(size_t)mm * 32 + 16 + r] = __float2bfloat16(0.f);
}

// ---------------- main GEMM: mma.sync bf16 3-split, 128x256 tile ----------------
__device__ __forceinline__ void issue_chunk(uint32_t s, int idx,
                                            int rowBase, int colBase, int b, int tid) {
    const __nv_bfloat16 *ah, *al, *bh, *bl;
    int sA, sB;
    if (idx < NCHUNK) {
        size_t ko = (size_t)idx * CK;
        ah = g_xh + (size_t)rowBase * NDIN + ko;
        al = g_xl + (size_t)rowBase * NDIN + ko;
        bh = g_wh + (size_t)colBase * NDIN + ko;
        bl = g_wl + (size_t)colBase * NDIN + ko;
        sA = NDIN; sB = NDIN;
    } else {  // LoRA virtual chunk (K=16 zero-padded to 32)
        ah = g_lxh + (size_t)rowBase * 32;
        al = g_lxl + (size_t)rowBase * 32;
        bh = g_cbh + ((size_t)b * NDOUT + colBase) * 32;
        bl = g_cbl + ((size_t)b * NDOUT + colBase) * 32;
        sA = 32; sB = 32;
    }
    // A: 128 rows x 4 chunks -> 2 per thread (hi & lo)
#pragma unroll
    for (int j = 0; j < 2; j++) {
        int id = tid + 256 * j;
        int row = id >> 2, ch = id & 3;
        uint32_t so = swof(row, ch);
        const __nv_bfloat16* gp = ah + (size_t)row * sA + ch * 8;
        cp16(s + so, gp);
        cp16(s + OF_AL + so, al + (size_t)row * sA + ch * 8);
    }
    // B: 256 rows x 4 chunks -> 4 per thread (hi & lo)
#pragma unroll
    for (int j = 0; j < 4; j++) {
        int id = tid + 256 * j;
        int row = id >> 2, ch = id & 3;
        uint32_t so = swof(row, ch);
        cp16(s + OF_BH + so, bh + (size_t)row * sB + ch * 8);
        cp16(s + OF_BL + so, bl + (size_t)row * sB + ch * 8);
    }
}

__global__ void __launch_bounds__(256, 1) k_gemm(float* __restrict__ out) {
    extern __shared__ char smem[];
    const uint32_t sb0 = smem_u32(smem);
    const int tid = threadIdx.x;
    const int wid = tid >> 5, lane = tid & 31;
    const int wm = wid >> 2, wn = wid & 3;      // 2x4 warp grid, warp tile 64x64
    const int rowBase = blockIdx.y * BM;
    const int colBase = blockIdx.x * BN;
    const int b = blockIdx.y >> 5;              // NS/BM = 32 row-blocks per batch
    const int lr = lane & 15, lc = lane >> 4;

    float acc[4][8][4];
#pragma unroll
    for (int i = 0; i < 4; i++)
#pragma unroll
        for (int j = 0; j < 8; j++)
#pragma unroll
            for (int q = 0; q < 4; q++) acc[i][j][q] = 0.f;

    issue_chunk(sb0 + 0 * STAGE_SZ, 0, rowBase, colBase, b, tid); cp_commit();
    issue_chunk(sb0 + 1 * STAGE_SZ, 1, rowBase, colBase, b, tid); cp_commit();
    issue_chunk(sb0 + 2 * STAGE_SZ, 2, rowBase, colBase, b, tid); cp_commit();

    for (int kc = 0; kc < NCHTOT; kc++) {
        if (kc + 3 < NCHTOT)
            issue_chunk(sb0 + ((kc + 3) & 3) * STAGE_SZ, kc + 3, rowBase, colBase, b, tid);
        cp_commit();
        cp_wait3();
        __syncthreads();

        const uint32_t Sb = sb0 + (kc & 3) * STAGE_SZ;
#pragma unroll
        for (int ks = 0; ks < 2; ks++) {
            const int ck = ks * 2 + lc;
            // B fragments: 8 n-tiles (4x ldmatrix.x4 over 16 n-rows), hi and lo
            uint32_t bh_[8][2], bl_[8][2];
#pragma unroll
            for (int bp = 0; bp < 4; bp++) {
                int row = wn * 64 + bp * 16 + lr;
                uint32_t ad = Sb + OF_BH + swof(row, ck);
                uint32_t r0, r1, r2, r3;
                LDSM4(r0, r1, r2, r3, ad);
                bh_[bp * 2 + 0][0] = r0; bh_[bp * 2 + 0][1] = r2;
                bh_[bp * 2 + 1][0] = r1; bh_[bp * 2 + 1][1] = r3;
                LDSM4(r0, r1, r2, r3, ad + B_SZ);
                bl_[bp * 2 + 0][0] = r0; bl_[bp * 2 + 0][1] = r2;
                bl_[bp * 2 + 1][0] = r1; bl_[bp * 2 + 1][1] = r3;
            }
#pragma unroll
            for (int mt = 0; mt < 4; mt++) {
                int row = wm * 64 + mt * 16 + lr;
                uint32_t aad = Sb + swof(row, ck);
                uint32_t a_h[4], a_l[4];
                LDSM4(a_h[0], a_h[1], a_h[2], a_h[3], aad);
                LDSM4(a_l[0], a_l[1], a_l[2], a_l[3], aad + A_SZ);
#pragma unroll
                for (int nt = 0; nt < 8; nt++) {
                    MMA16816(acc[mt][nt], a_h, bh_[nt][0], bh_[nt][1]);
                    MMA16816(acc[mt][nt], a_h, bl_[nt][0], bl_[nt][1]);
                    MMA16816(acc[mt][nt], a_l, bh_[nt][0], bh_[nt][1]);
                }
            }
        }
        __syncthreads();
    }

    // ---------------- epilogue: write fp32 ----------------
#pragma unroll
    for (int mt = 0; mt < 4; mt++) {
#pragma unroll
        for (int nt = 0; nt < 8; nt++) {
            int row = rowBase + wm * 64 + mt * 16 + (lane >> 2);
            int col = colBase + wn * 64 + nt * 8 + (lane & 3) * 2;
            *(float2*)&out[(size_t)row * NDOUT + col] =
                make_float2(acc[mt][nt][0], acc[mt][nt][1]);
            *(float2*)&out[(size_t)(row + 8) * NDOUT + col] =
                make_float2(acc[mt][nt][2], acc[mt][nt][3]);
        }
    }
}

// ---------------- launch ----------------
extern "C" void kernel_launch(void* const* d_in, const int* in_sizes, int n_in,
                              void* d_out, int out_size) {
    const float* x      = (const float*)d_in[0];
    const float* gate   = (const float*)d_in[1];
    const float* W_org  = (const float*)d_in[2];
    const float* W_down = (const float*)d_in[3];
    const float* W_up   = (const float*)d_in[4];
    float* out = (float*)d_out;

    cudaFuncSetAttribute(k_gemm, cudaFuncAttributeMaxDynamicSharedMemorySize, SMEM_TOTAL);

    k_split_x<<<(size_t)NM * NDIN / 2048, 256>>>(x);
    k_split_w<<<(size_t)NDOUT * NDIN / 2048, 256>>>(W_org);
    k_combine<<<(NB * NDOUT * NR + 255) / 256, 256>>>(gate, W_up);
    k_lx<<<NM / 32, 512>>>(x, W_down);

    dim3 grid(NDOUT / BN, NM / BM);   // (8, 128) = 1024 CTAs
    k_gemm<<<grid, 256, SMEM_TOTAL>>>(out);
}

// round 6
// speedup vs baseline: 2.4232x; 1.0703x over previous
#include <cuda_runtime.h>
#include <cuda_bf16.h>
#include <cstdint>

// ---------------- problem constants ----------------
#define NB 4
#define NS 4096
#define NDIN 2048
#define NDOUT 2048
#define NR 16
#define NE 12
#define NM (NB * NS)  // 16384

// ---------------- GEMM tiling ----------------
#define BM 128
#define BN 256
#define CK 32                    // K per chunk (bf16): 64B rows
#define NCHUNK (NDIN / CK)       // 64
#define NCHTOT (NCHUNK + 1)      // +1 virtual LoRA chunk
#define NSTAGE 4

#define A_SZ (BM * 64)                       // 8192
#define B_SZ (BN * 64)                       // 16384
#define OF_AL A_SZ
#define OF_BH (2 * A_SZ)
#define OF_BL (2 * A_SZ + B_SZ)
#define STAGE_SZ (2 * A_SZ + 2 * B_SZ)       // 49152
#define SMEM_TOTAL (NSTAGE * STAGE_SZ)       // 196608

// ---------------- scratch (device globals: allocation-free rule) ----------------
__device__ __align__(16) __nv_bfloat16 g_xh[(size_t)NM * NDIN];
__device__ __align__(16) __nv_bfloat16 g_xl[(size_t)NM * NDIN];
__device__ __align__(16) __nv_bfloat16 g_wh[(size_t)NDOUT * NDIN];
__device__ __align__(16) __nv_bfloat16 g_wl[(size_t)NDOUT * NDIN];
__device__ __align__(16) __nv_bfloat16 g_lxh[(size_t)NM * 32];        // [m][32], cols16+ = 0
__device__ __align__(16) __nv_bfloat16 g_lxl[(size_t)NM * 32];
__device__ __align__(16) __nv_bfloat16 g_cbh[(size_t)NB * NDOUT * 32];
__device__ __align__(16) __nv_bfloat16 g_cbl[(size_t)NB * NDOUT * 32];

// ---------------- PTX helpers (plain sm_80+ instructions only) ----------------
__device__ __forceinline__ uint32_t smem_u32(const void* p) {
    uint32_t a;
    asm("{ .reg .u64 t; cvta.to.shared.u64 t, %1; cvt.u32.u64 %0, t; }" : "=r"(a) : "l"(p));
    return a;
}
__device__ __forceinline__ void cp16(uint32_t saddr, const void* gptr) {
    asm volatile("cp.async.cg.shared.global [%0], [%1], 16;"
                 :: "r"(saddr), "l"(__cvta_generic_to_global(gptr)) : "memory");
}
__device__ __forceinline__ void cp_commit() {
    asm volatile("cp.async.commit_group;" ::: "memory");
}
__device__ __forceinline__ void cp_wait2() {
    asm volatile("cp.async.wait_group 2;" ::: "memory");
}
__device__ __forceinline__ void cp_wait1() {
    asm volatile("cp.async.wait_group 1;" ::: "memory");
}
#define LDSM4(r0, r1, r2, r3, addr)                                              \
    asm volatile("ldmatrix.sync.aligned.m8n8.x4.shared.b16 {%0,%1,%2,%3}, [%4];" \
                 : "=r"(r0), "=r"(r1), "=r"(r2), "=r"(r3) : "r"(addr))
#define MMA16816(c, a, b0, b1)                                                \
    asm volatile("mma.sync.aligned.m16n8k16.row.col.f32.bf16.bf16.f32 "       \
                 "{%0,%1,%2,%3},{%4,%5,%6,%7},{%8,%9},{%0,%1,%2,%3};"         \
                 : "+f"((c)[0]), "+f"((c)[1]), "+f"((c)[2]), "+f"((c)[3])     \
                 : "r"((a)[0]), "r"((a)[1]), "r"((a)[2]), "r"((a)[3]),        \
                   "r"(b0), "r"(b1))

// 64B-row swizzle: 16B-chunk' = chunk ^ ((row>>1)&3)
__device__ __forceinline__ uint32_t swof(int row, int ch) {
    return (uint32_t)(row * 64 + ((ch ^ ((row >> 1) & 3)) << 4));
}

// ---------------- pre-kernels ----------------
union BF8 { __nv_bfloat16 b[8]; uint4 u; };

__device__ __forceinline__ void split8(const float* src, __nv_bfloat16* hi,
                                       __nv_bfloat16* lo, size_t i) {
    float f[8];
    float4 v0 = *(const float4*)(src + i);
    float4 v1 = *(const float4*)(src + i + 4);
    f[0]=v0.x; f[1]=v0.y; f[2]=v0.z; f[3]=v0.w;
    f[4]=v1.x; f[5]=v1.y; f[6]=v1.z; f[7]=v1.w;
    BF8 h, l;
#pragma unroll
    for (int j = 0; j < 8; j++) {
        h.b[j] = __float2bfloat16(f[j]);
        l.b[j] = __float2bfloat16(f[j] - __bfloat162float(h.b[j]));
    }
    *(uint4*)(hi + i) = h.u;
    *(uint4*)(lo + i) = l.u;
}
__global__ void k_split_x(const float* __restrict__ x) {
    size_t i = ((size_t)blockIdx.x * 256 + threadIdx.x) * 8;
    split8(x, g_xh, g_xl, i);
}

// fused: blocks [0,2048) split W_org; blocks [2048,2560) do gate-combine
__global__ void k_split_w_comb(const float* __restrict__ W_org,
                               const float* __restrict__ gate,
                               const float* __restrict__ W_up) {
    if (blockIdx.x < 2048) {
        size_t i = ((size_t)blockIdx.x * 256 + threadIdx.x) * 8;
        split8(W_org, g_wh, g_wl, i);
    } else {
        int idx = (blockIdx.x - 2048) * 256 + threadIdx.x;
        if (idx >= NB * NDOUT * NR) return;
        int b = idx / (NDOUT * NR);
        int orr = idx - b * (NDOUT * NR);
        int o = orr >> 4, r = orr & 15;
        float s = 0.f;
#pragma unroll
        for (int e = 0; e < NE; e++)
            s += __ldg(&gate[b * NE + e]) * __ldg(&W_up[(size_t)e * NDOUT * NR + orr]);
        size_t off = ((size_t)b * NDOUT + o) * 32;
        __nv_bfloat16 h = __float2bfloat16(s);
        g_cbh[off + r] = h;
        g_cbl[off + r] = __float2bfloat16(s - __bfloat162float(h));
        g_cbh[off + 16 + r] = __float2bfloat16(0.f);
        g_cbl[off + 16 + r] = __float2bfloat16(0.f);
    }
}

// ---------------- k_lx: lx[m,0:16] = x @ W_down^T via mma (3-split) ----------------
// smem: [0,64K) wd_hi tiles; [64K,128K) wd_lo; [128K,+3*32K) x stages (xh 16K + xl 16K)
#define LX_WSL 65536
#define LX_XS  131072
#define LX_STGSZ 32768
#define LX_SMEM (131072 + 3 * 32768)   // 229376

__device__ __forceinline__ void lx_issue(uint32_t sb, int s, int c, int rowBase, int tid) {
    uint32_t xs = sb + LX_XS + s * LX_STGSZ;
    const __nv_bfloat16* xh = g_xh + (size_t)rowBase * NDIN + c * 64;
    const __nv_bfloat16* xl = g_xl + (size_t)rowBase * NDIN + c * 64;
#pragma unroll
    for (int j = 0; j < 8; j++) {
        int g = tid + 128 * j;
        int row = g >> 3, ch = g & 7;
        uint32_t so = row * 128 + ((ch ^ (row & 7)) << 4);
        cp16(xs + so, xh + (size_t)row * NDIN + ch * 8);
        cp16(xs + 16384 + so, xl + (size_t)row * NDIN + ch * 8);
    }
}

__global__ void __launch_bounds__(128, 1) k_lx(const float* __restrict__ Wd) {
    extern __shared__ char sm[];
    const uint32_t sb = smem_u32(sm);
    const int tid = threadIdx.x;
    const int w = tid >> 5, lane = tid & 31;
    const int rowBase = blockIdx.x * 128;

    // stage W_down fp32 -> bf16 hi/lo tiles: off = kt*512 + n*32 + half*16 + kk*2
    for (int idx = tid; idx < 16 * 1024; idx += 128) {
        int n = idx >> 10;
        int k2 = (idx & 1023) * 2;
        float2 wv = *(const float2*)(Wd + (size_t)n * NDIN + k2);
        __nv_bfloat16 h0 = __float2bfloat16(wv.x);
        __nv_bfloat16 h1 = __float2bfloat16(wv.y);
        __nv_bfloat16 l0 = __float2bfloat16(wv.x - __bfloat162float(h0));
        __nv_bfloat16 l1 = __float2bfloat16(wv.y - __bfloat162float(h1));
        int kt = k2 >> 4, kin = k2 & 15;
        uint32_t off = kt * 512 + n * 32 + (kin >> 3) * 16 + (kin & 7) * 2;
        *(__nv_bfloat162*)(sm + off) = __halves2bfloat162(h0, h1);
        *(__nv_bfloat162*)(sm + LX_WSL + off) = __halves2bfloat162(l0, l1);
    }

    float acc[2][2][4];
#pragma unroll
    for (int i = 0; i < 2; i++)
#pragma unroll
        for (int j = 0; j < 2; j++)
#pragma unroll
            for (int q = 0; q < 4; q++) acc[i][j][q] = 0.f;

    lx_issue(sb, 0, 0, rowBase, tid); cp_commit();
    lx_issue(sb, 1, 1, rowBase, tid); cp_commit();

    const int lr = lane & 15, lc = lane >> 4;
    for (int c = 0; c < 32; c++) {
        cp_wait1();
        __syncthreads();
        if (c + 2 < 32) lx_issue(sb, (c + 2) % 3, c + 2, rowBase, tid);
        cp_commit();
        const uint32_t xs = sb + LX_XS + (c % 3) * LX_STGSZ;
#pragma unroll
        for (int ks = 0; ks < 4; ks++) {
            int kt = c * 4 + ks;
            uint32_t bad = sb + kt * 512 + lr * 32 + lc * 16;
            uint32_t r0, r1, r2, r3;
            LDSM4(r0, r1, r2, r3, bad);
            uint32_t bh0[2] = {r0, r2}, bh1[2] = {r1, r3};
            LDSM4(r0, r1, r2, r3, bad + LX_WSL);
            uint32_t bl0[2] = {r0, r2}, bl1[2] = {r1, r3};
#pragma unroll
            for (int mt = 0; mt < 2; mt++) {
                int row = w * 32 + mt * 16 + lr;
                uint32_t aad = xs + row * 128 + (((ks * 2 + lc) ^ (row & 7)) << 4);
                uint32_t ah[4], al[4];
                LDSM4(ah[0], ah[1], ah[2], ah[3], aad);
                LDSM4(al[0], al[1], al[2], al[3], aad + 16384);
                MMA16816(acc[mt][0], ah, bh0[0], bh0[1]);
                MMA16816(acc[mt][1], ah, bh1[0], bh1[1]);
                MMA16816(acc[mt][0], ah, bl0[0], bl0[1]);
                MMA16816(acc[mt][1], ah, bl1[0], bl1[1]);
                MMA16816(acc[mt][0], al, bh0[0], bh0[1]);
                MMA16816(acc[mt][1], al, bh1[0], bh1[1]);
            }
        }
    }

    // epilogue: split to hi/lo, zero pad cols 16-31
#pragma unroll
    for (int mt = 0; mt < 2; mt++) {
        int row0 = rowBase + w * 32 + mt * 16 + (lane >> 2);
#pragma unroll
        for (int nt = 0; nt < 2; nt++) {
            int col = nt * 8 + (lane & 3) * 2;
#pragma unroll
            for (int half = 0; half < 2; half++) {
                int m = row0 + half * 8;
                float v0 = acc[mt][nt][half * 2 + 0];
                float v1 = acc[mt][nt][half * 2 + 1];
                __nv_bfloat16 h0 = __float2bfloat16(v0);
                __nv_bfloat16 h1 = __float2bfloat16(v1);
                *(__nv_bfloat162*)&g_lxh[(size_t)m * 32 + col] = __halves2bfloat162(h0, h1);
                *(__nv_bfloat162*)&g_lxl[(size_t)m * 32 + col] = __halves2bfloat162(
                    __float2bfloat16(v0 - __bfloat162float(h0)),
                    __float2bfloat16(v1 - __bfloat162float(h1)));
            }
        }
    }
    {
        int m = rowBase + w * 32 + lane;
        uint4 z = make_uint4(0, 0, 0, 0);
        *(uint4*)&g_lxh[(size_t)m * 32 + 16] = z;
        *(uint4*)&g_lxh[(size_t)m * 32 + 24] = z;
        *(uint4*)&g_lxl[(size_t)m * 32 + 16] = z;
        *(uint4*)&g_lxl[(size_t)m * 32 + 24] = z;
    }
}

// ---------------- main GEMM: mma.sync bf16 3-split, 128x256 tile ----------------
__device__ __forceinline__ void issue_chunk(uint32_t s, int idx,
                                            int rowBase, int colBase, int b, int tid) {
    const __nv_bfloat16 *ah, *al, *bh, *bl;
    int sA, sB;
    if (idx < NCHUNK) {
        size_t ko = (size_t)idx * CK;
        ah = g_xh + (size_t)rowBase * NDIN + ko;
        al = g_xl + (size_t)rowBase * NDIN + ko;
        bh = g_wh + (size_t)colBase * NDIN + ko;
        bl = g_wl + (size_t)colBase * NDIN + ko;
        sA = NDIN; sB = NDIN;
    } else {  // LoRA virtual chunk (K=16 zero-padded to 32)
        ah = g_lxh + (size_t)rowBase * 32;
        al = g_lxl + (size_t)rowBase * 32;
        bh = g_cbh + ((size_t)b * NDOUT + colBase) * 32;
        bl = g_cbl + ((size_t)b * NDOUT + colBase) * 32;
        sA = 32; sB = 32;
    }
#pragma unroll
    for (int j = 0; j < 2; j++) {
        int id = tid + 256 * j;
        int row = id >> 2, ch = id & 3;
        uint32_t so = swof(row, ch);
        cp16(s + so, ah + (size_t)row * sA + ch * 8);
        cp16(s + OF_AL + so, al + (size_t)row * sA + ch * 8);
    }
#pragma unroll
    for (int j = 0; j < 4; j++) {
        int id = tid + 256 * j;
        int row = id >> 2, ch = id & 3;
        uint32_t so = swof(row, ch);
        cp16(s + OF_BH + so, bh + (size_t)row * sB + ch * 8);
        cp16(s + OF_BL + so, bl + (size_t)row * sB + ch * 8);
    }
}

__global__ void __launch_bounds__(256, 1) k_gemm(float* __restrict__ out) {
    extern __shared__ char smem[];
    const uint32_t sb0 = smem_u32(smem);
    const int tid = threadIdx.x;
    const int wid = tid >> 5, lane = tid & 31;
    const int wm = wid >> 2, wn = wid & 3;      // 2x4 warp grid, warp tile 64x64
    const int rowBase = blockIdx.y * BM;
    const int colBase = blockIdx.x * BN;
    const int b = blockIdx.y >> 5;
    const int lr = lane & 15, lc = lane >> 4;

    float acc[4][8][4];
#pragma unroll
    for (int i = 0; i < 4; i++)
#pragma unroll
        for (int j = 0; j < 8; j++)
#pragma unroll
            for (int q = 0; q < 4; q++) acc[i][j][q] = 0.f;

    issue_chunk(sb0 + 0 * STAGE_SZ, 0, rowBase, colBase, b, tid); cp_commit();
    issue_chunk(sb0 + 1 * STAGE_SZ, 1, rowBase, colBase, b, tid); cp_commit();
    issue_chunk(sb0 + 2 * STAGE_SZ, 2, rowBase, colBase, b, tid); cp_commit();

    for (int kc = 0; kc < NCHTOT; kc++) {
        cp_wait2();
        __syncthreads();
        // single-sync multistage: safe to overwrite slot (kc-1)&3 now
        if (kc + 3 < NCHTOT)
            issue_chunk(sb0 + ((kc + 3) & 3) * STAGE_SZ, kc + 3, rowBase, colBase, b, tid);
        cp_commit();

        const uint32_t Sb = sb0 + (kc & 3) * STAGE_SZ;
#pragma unroll
        for (int ks = 0; ks < 2; ks++) {
            const int ck = ks * 2 + lc;
            uint32_t bh_[8][2], bl_[8][2];
#pragma unroll
            for (int bp = 0; bp < 4; bp++) {
                int row = wn * 64 + bp * 16 + lr;
                uint32_t ad = Sb + OF_BH + swof(row, ck);
                uint32_t r0, r1, r2, r3;
                LDSM4(r0, r1, r2, r3, ad);
                bh_[bp * 2 + 0][0] = r0; bh_[bp * 2 + 0][1] = r2;
                bh_[bp * 2 + 1][0] = r1; bh_[bp * 2 + 1][1] = r3;
                LDSM4(r0, r1, r2, r3, ad + B_SZ);
                bl_[bp * 2 + 0][0] = r0; bl_[bp * 2 + 0][1] = r2;
                bl_[bp * 2 + 1][0] = r1; bl_[bp * 2 + 1][1] = r3;
            }
#pragma unroll
            for (int mt = 0; mt < 4; mt++) {
                int row = wm * 64 + mt * 16 + lr;
                uint32_t aad = Sb + swof(row, ck);
                uint32_t a_h[4], a_l[4];
                LDSM4(a_h[0], a_h[1], a_h[2], a_h[3], aad);
                LDSM4(a_l[0], a_l[1], a_l[2], a_l[3], aad + A_SZ);
#pragma unroll
                for (int nt = 0; nt < 8; nt++) {
                    MMA16816(acc[mt][nt], a_h, bh_[nt][0], bh_[nt][1]);
                    MMA16816(acc[mt][nt], a_h, bl_[nt][0], bl_[nt][1]);
                    MMA16816(acc[mt][nt], a_l, bh_[nt][0], bh_[nt][1]);
                }
            }
        }
    }

    // ---------------- epilogue ----------------
#pragma unroll
    for (int mt = 0; mt < 4; mt++) {
#pragma unroll
        for (int nt = 0; nt < 8; nt++) {
            int row = rowBase + wm * 64 + mt * 16 + (lane >> 2);
            int col = colBase + wn * 64 + nt * 8 + (lane & 3) * 2;
            *(float2*)&out[(size_t)row * NDOUT + col] =
                make_float2(acc[mt][nt][0], acc[mt][nt][1]);
            *(float2*)&out[(size_t)(row + 8) * NDOUT + col] =
                make_float2(acc[mt][nt][2], acc[mt][nt][3]);
        }
    }
}

// ---------------- launch ----------------
extern "C" void kernel_launch(void* const* d_in, const int* in_sizes, int n_in,
                              void* d_out, int out_size) {
    const float* x      = (const float*)d_in[0];
    const float* gate   = (const float*)d_in[1];
    const float* W_org  = (const float*)d_in[2];
    const float* W_down = (const float*)d_in[3];
    const float* W_up   = (const float*)d_in[4];
    float* out = (float*)d_out;

    cudaFuncSetAttribute(k_gemm, cudaFuncAttributeMaxDynamicSharedMemorySize, SMEM_TOTAL);
    cudaFuncSetAttribute(k_lx, cudaFuncAttributeMaxDynamicSharedMemorySize, LX_SMEM);

    k_split_x<<<(size_t)NM * NDIN / 2048, 256>>>(x);
    k_split_w_comb<<<2048 + 512, 256>>>(W_org, gate, W_up);
    k_lx<<<NM / 128, 128, LX_SMEM>>>(W_down);

    dim3 grid(NDOUT / BN, NM / BM);   // (8, 128) = 1024 CTAs
    k_gemm<<<grid, 256, SMEM_TOTAL>>>(out);
}

// round 7
// speedup vs baseline: 2.5697x; 1.0604x over previous
#include <cuda_runtime.h>
#include <cuda_bf16.h>
#include <cstdint>

// ---------------- problem constants ----------------
#define NB 4
#define NS 4096
#define NDIN 2048
#define NDOUT 2048
#define NR 16
#define NE 12
#define NM (NB * NS)  // 16384

// ---------------- GEMM tiling ----------------
#define BM 128
#define BN 128
#define CK 32                    // K per chunk (bf16): 64B rows
#define NCHUNK (NDIN / CK)       // 64
#define NCHTOT (NCHUNK + 1)      // +1 virtual LoRA chunk
#define NSTAGE 3

#define PART_SZ 8192                         // 128 rows x 64B
#define OF_AL PART_SZ
#define OF_BH (2 * PART_SZ)
#define OF_BL (3 * PART_SZ)
#define STAGE_SZ (4 * PART_SZ)               // 32768
#define SMEM_TOTAL (NSTAGE * STAGE_SZ)       // 98304 (x2 CTAs = 192KB/SM)

// ---------------- scratch (device globals: allocation-free rule) ----------------
__device__ __align__(16) __nv_bfloat16 g_xh[(size_t)NM * NDIN];
__device__ __align__(16) __nv_bfloat16 g_xl[(size_t)NM * NDIN];
__device__ __align__(16) __nv_bfloat16 g_wh[(size_t)NDOUT * NDIN];
__device__ __align__(16) __nv_bfloat16 g_wl[(size_t)NDOUT * NDIN];
__device__ __align__(16) __nv_bfloat16 g_lxh[(size_t)NM * 32];        // [m][32], cols16+ = 0
__device__ __align__(16) __nv_bfloat16 g_lxl[(size_t)NM * 32];
__device__ __align__(16) __nv_bfloat16 g_cbh[(size_t)NB * NDOUT * 32];
__device__ __align__(16) __nv_bfloat16 g_cbl[(size_t)NB * NDOUT * 32];

// ---------------- PTX helpers (plain sm_80+ instructions only) ----------------
__device__ __forceinline__ uint32_t smem_u32(const void* p) {
    uint32_t a;
    asm("{ .reg .u64 t; cvta.to.shared.u64 t, %1; cvt.u32.u64 %0, t; }" : "=r"(a) : "l"(p));
    return a;
}
__device__ __forceinline__ void cp16(uint32_t saddr, const void* gptr) {
    asm volatile("cp.async.cg.shared.global [%0], [%1], 16;"
                 :: "r"(saddr), "l"(__cvta_generic_to_global(gptr)) : "memory");
}
__device__ __forceinline__ void cp_commit() {
    asm volatile("cp.async.commit_group;" ::: "memory");
}
__device__ __forceinline__ void cp_wait1() {
    asm volatile("cp.async.wait_group 1;" ::: "memory");
}
#define LDSM4(r0, r1, r2, r3, addr)                                              \
    asm volatile("ldmatrix.sync.aligned.m8n8.x4.shared.b16 {%0,%1,%2,%3}, [%4];" \
                 : "=r"(r0), "=r"(r1), "=r"(r2), "=r"(r3) : "r"(addr))
#define MMA16816(c, a, b0, b1)                                                \
    asm volatile("mma.sync.aligned.m16n8k16.row.col.f32.bf16.bf16.f32 "       \
                 "{%0,%1,%2,%3},{%4,%5,%6,%7},{%8,%9},{%0,%1,%2,%3};"         \
                 : "+f"((c)[0]), "+f"((c)[1]), "+f"((c)[2]), "+f"((c)[3])     \
                 : "r"((a)[0]), "r"((a)[1]), "r"((a)[2]), "r"((a)[3]),        \
                   "r"(b0), "r"(b1))

// 64B-row swizzle: 16B-chunk' = chunk ^ ((row>>1)&3)
__device__ __forceinline__ uint32_t swof(int row, int ch) {
    return (uint32_t)(row * 64 + ((ch ^ ((row >> 1) & 3)) << 4));
}
// swizzle base for fixed row (chunk folded in later via XOR on bits [4:6))
__device__ __forceinline__ uint32_t swbase(int row) {
    return (uint32_t)(row * 64 + (((row >> 1) & 3) << 4));
}

// ---------------- pre-kernels ----------------
__device__ __forceinline__ void split8(const float* src, __nv_bfloat16* hi,
                                       __nv_bfloat16* lo, size_t i) {
    float f[8];
    float4 v0 = *(const float4*)(src + i);
    float4 v1 = *(const float4*)(src + i + 4);
    f[0]=v0.x; f[1]=v0.y; f[2]=v0.z; f[3]=v0.w;
    f[4]=v1.x; f[5]=v1.y; f[6]=v1.z; f[7]=v1.w;
    union { __nv_bfloat16 b[8]; uint4 u; } h, l;
#pragma unroll
    for (int j = 0; j < 8; j++) {
        h.b[j] = __float2bfloat16(f[j]);
        l.b[j] = __float2bfloat16(f[j] - __bfloat162float(h.b[j]));
    }
    *(uint4*)(hi + i) = h.u;
    *(uint4*)(lo + i) = l.u;
}
__global__ void k_split_x(const float* __restrict__ x) {
    size_t i = ((size_t)blockIdx.x * 256 + threadIdx.x) * 8;
    split8(x, g_xh, g_xl, i);
}

// fused: blocks [0,2048) split W_org; blocks [2048,2560) do gate-combine
__global__ void k_split_w_comb(const float* __restrict__ W_org,
                               const float* __restrict__ gate,
                               const float* __restrict__ W_up) {
    if (blockIdx.x < 2048) {
        size_t i = ((size_t)blockIdx.x * 256 + threadIdx.x) * 8;
        split8(W_org, g_wh, g_wl, i);
    } else {
        int idx = (blockIdx.x - 2048) * 256 + threadIdx.x;
        if (idx >= NB * NDOUT * NR) return;
        int b = idx / (NDOUT * NR);
        int orr = idx - b * (NDOUT * NR);
        int o = orr >> 4, r = orr & 15;
        float s = 0.f;
#pragma unroll
        for (int e = 0; e < NE; e++)
            s += __ldg(&gate[b * NE + e]) * __ldg(&W_up[(size_t)e * NDOUT * NR + orr]);
        size_t off = ((size_t)b * NDOUT + o) * 32;
        __nv_bfloat16 h = __float2bfloat16(s);
        g_cbh[off + r] = h;
        g_cbl[off + r] = __float2bfloat16(s - __bfloat162float(h));
        g_cbh[off + 16 + r] = __float2bfloat16(0.f);
        g_cbl[off + 16 + r] = __float2bfloat16(0.f);
    }
}

// ---------------- k_lx: lx[m,0:16] = x @ W_down^T via mma (3-split) ----------------
#define LX_WSL 65536
#define LX_XS  131072
#define LX_STGSZ 32768
#define LX_SMEM (131072 + 3 * 32768)   // 229376

__device__ __forceinline__ void lx_issue(uint32_t sb, int s, int c, int rowBase, int tid) {
    uint32_t xs = sb + LX_XS + s * LX_STGSZ;
    const __nv_bfloat16* xh = g_xh + (size_t)rowBase * NDIN + c * 64;
    const __nv_bfloat16* xl = g_xl + (size_t)rowBase * NDIN + c * 64;
#pragma unroll
    for (int j = 0; j < 8; j++) {
        int g = tid + 128 * j;
        int row = g >> 3, ch = g & 7;
        uint32_t so = row * 128 + ((ch ^ (row & 7)) << 4);
        cp16(xs + so, xh + (size_t)row * NDIN + ch * 8);
        cp16(xs + 16384 + so, xl + (size_t)row * NDIN + ch * 8);
    }
}

__global__ void __launch_bounds__(128, 1) k_lx(const float* __restrict__ Wd) {
    extern __shared__ char sm[];
    const uint32_t sb = smem_u32(sm);
    const int tid = threadIdx.x;
    const int w = tid >> 5, lane = tid & 31;
    const int rowBase = blockIdx.x * 128;

    for (int idx = tid; idx < 16 * 1024; idx += 128) {
        int n = idx >> 10;
        int k2 = (idx & 1023) * 2;
        float2 wv = *(const float2*)(Wd + (size_t)n * NDIN + k2);
        __nv_bfloat16 h0 = __float2bfloat16(wv.x);
        __nv_bfloat16 h1 = __float2bfloat16(wv.y);
        __nv_bfloat16 l0 = __float2bfloat16(wv.x - __bfloat162float(h0));
        __nv_bfloat16 l1 = __float2bfloat16(wv.y - __bfloat162float(h1));
        int kt = k2 >> 4, kin = k2 & 15;
        uint32_t off = kt * 512 + n * 32 + (kin >> 3) * 16 + (kin & 7) * 2;
        *(__nv_bfloat162*)(sm + off) = __halves2bfloat162(h0, h1);
        *(__nv_bfloat162*)(sm + LX_WSL + off) = __halves2bfloat162(l0, l1);
    }

    float acc[2][2][4];
#pragma unroll
    for (int i = 0; i < 2; i++)
#pragma unroll
        for (int j = 0; j < 2; j++)
#pragma unroll
            for (int q = 0; q < 4; q++) acc[i][j][q] = 0.f;

    lx_issue(sb, 0, 0, rowBase, tid); cp_commit();
    lx_issue(sb, 1, 1, rowBase, tid); cp_commit();

    const int lr = lane & 15, lc = lane >> 4;
    for (int c = 0; c < 32; c++) {
        cp_wait1();
        __syncthreads();
        if (c + 2 < 32) lx_issue(sb, (c + 2) % 3, c + 2, rowBase, tid);
        cp_commit();
        const uint32_t xs = sb + LX_XS + (c % 3) * LX_STGSZ;
#pragma unroll
        for (int ks = 0; ks < 4; ks++) {
            int kt = c * 4 + ks;
            uint32_t bad = sb + kt * 512 + lr * 32 + lc * 16;
            uint32_t r0, r1, r2, r3;
            LDSM4(r0, r1, r2, r3, bad);
            uint32_t bh0[2] = {r0, r2}, bh1[2] = {r1, r3};
            LDSM4(r0, r1, r2, r3, bad + LX_WSL);
            uint32_t bl0[2] = {r0, r2}, bl1[2] = {r1, r3};
#pragma unroll
            for (int mt = 0; mt < 2; mt++) {
                int row = w * 32 + mt * 16 + lr;
                uint32_t aad = xs + row * 128 + (((ks * 2 + lc) ^ (row & 7)) << 4);
                uint32_t ah[4], al[4];
                LDSM4(ah[0], ah[1], ah[2], ah[3], aad);
                LDSM4(al[0], al[1], al[2], al[3], aad + 16384);
                MMA16816(acc[mt][0], ah, bh0[0], bh0[1]);
                MMA16816(acc[mt][1], ah, bh1[0], bh1[1]);
                MMA16816(acc[mt][0], ah, bl0[0], bl0[1]);
                MMA16816(acc[mt][1], ah, bl1[0], bl1[1]);
                MMA16816(acc[mt][0], al, bh0[0], bh0[1]);
                MMA16816(acc[mt][1], al, bh1[0], bh1[1]);
            }
        }
    }

#pragma unroll
    for (int mt = 0; mt < 2; mt++) {
        int row0 = rowBase + w * 32 + mt * 16 + (lane >> 2);
#pragma unroll
        for (int nt = 0; nt < 2; nt++) {
            int col = nt * 8 + (lane & 3) * 2;
#pragma unroll
            for (int half = 0; half < 2; half++) {
                int m = row0 + half * 8;
                float v0 = acc[mt][nt][half * 2 + 0];
                float v1 = acc[mt][nt][half * 2 + 1];
                __nv_bfloat16 h0 = __float2bfloat16(v0);
                __nv_bfloat16 h1 = __float2bfloat16(v1);
                *(__nv_bfloat162*)&g_lxh[(size_t)m * 32 + col] = __halves2bfloat162(h0, h1);
                *(__nv_bfloat162*)&g_lxl[(size_t)m * 32 + col] = __halves2bfloat162(
                    __float2bfloat16(v0 - __bfloat162float(h0)),
                    __float2bfloat16(v1 - __bfloat162float(h1)));
            }
        }
    }
    {
        int m = rowBase + w * 32 + lane;
        uint4 z = make_uint4(0, 0, 0, 0);
        *(uint4*)&g_lxh[(size_t)m * 32 + 16] = z;
        *(uint4*)&g_lxh[(size_t)m * 32 + 24] = z;
        *(uint4*)&g_lxl[(size_t)m * 32 + 16] = z;
        *(uint4*)&g_lxl[(size_t)m * 32 + 24] = z;
    }
}

// ---------------- main GEMM: 128x128 tile, 2 CTAs/SM ----------------
__device__ __forceinline__ void issue_chunk(uint32_t s, int idx,
                                            int rowBase, int colBase, int b, int tid) {
    const __nv_bfloat16 *ah, *al, *bh, *bl;
    int ld;
    if (idx < NCHUNK) {
        size_t ko = (size_t)idx * CK;
        ah = g_xh + (size_t)rowBase * NDIN + ko;
        al = g_xl + (size_t)rowBase * NDIN + ko;
        bh = g_wh + (size_t)colBase * NDIN + ko;
        bl = g_wl + (size_t)colBase * NDIN + ko;
        ld = NDIN;
    } else {  // LoRA virtual chunk (K=16 zero-padded to 32)
        ah = g_lxh + (size_t)rowBase * 32;
        al = g_lxl + (size_t)rowBase * 32;
        bh = g_cbh + ((size_t)b * NDOUT + colBase) * 32;
        bl = g_cbl + ((size_t)b * NDOUT + colBase) * 32;
        ld = 32;
    }
    // 128 rows x 4 chunks each for A and B -> 2 j-iters per matrix (hi+lo)
#pragma unroll
    for (int j = 0; j < 2; j++) {
        int id = tid + 256 * j;
        int row = id >> 2, ch = id & 3;
        uint32_t so = swof(row, ch);
        size_t go = (size_t)row * ld + ch * 8;
        cp16(s + so, ah + go);
        cp16(s + OF_AL + so, al + go);
        cp16(s + OF_BH + so, bh + go);
        cp16(s + OF_BL + so, bl + go);
    }
}

__global__ void __launch_bounds__(256, 2) k_gemm(float* __restrict__ out) {
    extern __shared__ char smem[];
    const uint32_t sb0 = smem_u32(smem);
    const int tid = threadIdx.x;
    const int wid = tid >> 5, lane = tid & 31;
    const int wm = wid >> 2, wn = wid & 3;      // 2x4 warp grid, warp tile 64x32
    const int rowBase = blockIdx.y * BM;
    const int colBase = blockIdx.x * BN;
    const int b = blockIdx.y >> 5;              // NS/BM = 32 row-blocks per batch
    const int lr = lane & 15, lc = lane >> 4;

    // precomputed swizzle-base addresses (chunk XORed in per ks)
    uint32_t aBase[4], bBase[2];
#pragma unroll
    for (int mt = 0; mt < 4; mt++) aBase[mt] = swbase(wm * 64 + mt * 16 + lr);
#pragma unroll
    for (int bp = 0; bp < 2; bp++) bBase[bp] = OF_BH + swbase(wn * 32 + bp * 16 + lr);

    float acc[4][4][4];
#pragma unroll
    for (int i = 0; i < 4; i++)
#pragma unroll
        for (int j = 0; j < 4; j++)
#pragma unroll
            for (int q = 0; q < 4; q++) acc[i][j][q] = 0.f;

    issue_chunk(sb0 + 0 * STAGE_SZ, 0, rowBase, colBase, b, tid); cp_commit();
    issue_chunk(sb0 + 1 * STAGE_SZ, 1, rowBase, colBase, b, tid); cp_commit();

    int slot = 0;        // slot of chunk kc
    int nslot = 2;       // slot for chunk kc+2
    for (int kc = 0; kc < NCHTOT; kc++) {
        cp_wait1();
        __syncthreads();
        if (kc + 2 < NCHTOT)
            issue_chunk(sb0 + nslot * STAGE_SZ, kc + 2, rowBase, colBase, b, tid);
        cp_commit();

        const uint32_t Sb = sb0 + slot * STAGE_SZ;
        slot = (slot + 1 == NSTAGE) ? 0 : slot + 1;
        nslot = (nslot + 1 == NSTAGE) ? 0 : nslot + 1;
#pragma unroll
        for (int ks = 0; ks < 2; ks++) {
            const uint32_t cx = (uint32_t)(ks * 2 + lc) << 4;   // XOR bits [4:6)
            uint32_t bh_[4][2], bl_[4][2];
#pragma unroll
            for (int bp = 0; bp < 2; bp++) {
                uint32_t ad = Sb + (bBase[bp] ^ cx);
                uint32_t r0, r1, r2, r3;
                LDSM4(r0, r1, r2, r3, ad);
                bh_[bp * 2 + 0][0] = r0; bh_[bp * 2 + 0][1] = r2;
                bh_[bp * 2 + 1][0] = r1; bh_[bp * 2 + 1][1] = r3;
                LDSM4(r0, r1, r2, r3, ad + PART_SZ);
                bl_[bp * 2 + 0][0] = r0; bl_[bp * 2 + 0][1] = r2;
                bl_[bp * 2 + 1][0] = r1; bl_[bp * 2 + 1][1] = r3;
            }
#pragma unroll
            for (int mt = 0; mt < 4; mt++) {
                uint32_t aad = Sb + (aBase[mt] ^ cx);
                uint32_t a_h[4], a_l[4];
                LDSM4(a_h[0], a_h[1], a_h[2], a_h[3], aad);
                LDSM4(a_l[0], a_l[1], a_l[2], a_l[3], aad + PART_SZ);
#pragma unroll
                for (int nt = 0; nt < 4; nt++) {
                    MMA16816(acc[mt][nt], a_h, bh_[nt][0], bh_[nt][1]);
                    MMA16816(acc[mt][nt], a_h, bl_[nt][0], bl_[nt][1]);
                    MMA16816(acc[mt][nt], a_l, bh_[nt][0], bh_[nt][1]);
                }
            }
        }
    }

    // ---------------- epilogue ----------------
#pragma unroll
    for (int mt = 0; mt < 4; mt++) {
#pragma unroll
        for (int nt = 0; nt < 4; nt++) {
            int row = rowBase + wm * 64 + mt * 16 + (lane >> 2);
            int col = colBase + wn * 32 + nt * 8 + (lane & 3) * 2;
            *(float2*)&out[(size_t)row * NDOUT + col] =
                make_float2(acc[mt][nt][0], acc[mt][nt][1]);
            *(float2*)&out[(size_t)(row + 8) * NDOUT + col] =
                make_float2(acc[mt][nt][2], acc[mt][nt][3]);
        }
    }
}

// ---------------- launch ----------------
extern "C" void kernel_launch(void* const* d_in, const int* in_sizes, int n_in,
                              void* d_out, int out_size) {
    const float* x      = (const float*)d_in[0];
    const float* gate   = (const float*)d_in[1];
    const float* W_org  = (const float*)d_in[2];
    const float* W_down = (const float*)d_in[3];
    const float* W_up   = (const float*)d_in[4];
    float* out = (float*)d_out;

    cudaFuncSetAttribute(k_gemm, cudaFuncAttributeMaxDynamicSharedMemorySize, SMEM_TOTAL);
    cudaFuncSetAttribute(k_lx, cudaFuncAttributeMaxDynamicSharedMemorySize, LX_SMEM);

    k_split_x<<<(size_t)NM * NDIN / 2048, 256>>>(x);
    k_split_w_comb<<<2048 + 512, 256>>>(W_org, gate, W_up);
    k_lx<<<NM / 128, 128, LX_SMEM>>>(W_down);

    dim3 grid(NDOUT / BN, NM / BM);   // (16, 128) = 2048 CTAs
    k_gemm<<<grid, 256, SMEM_TOTAL>>>(out);
}

// round 8
// speedup vs baseline: 3.6671x; 1.4271x over previous
#include <cuda_runtime.h>
#include <cuda_bf16.h>
#include <cstdint>

// ---------------- problem constants ----------------
#define NB 4
#define NS 4096
#define NDIN 2048
#define NDOUT 2048
#define NR 16
#define NE 12
#define NM (NB * NS)  // 16384

// ---------------- GEMM tiling ----------------
#define BM 128
#define BN 128
#define CK 32                    // K per chunk (tf32): 128B rows
#define NCHUNK (NDIN / CK)       // 64
#define NCHTOT (NCHUNK + 1)      // +1 virtual LoRA chunk
#define NSTAGE 3

#define PART_SZ 16384                        // 128 rows x 128B
#define OF_B PART_SZ
#define STAGE_SZ (2 * PART_SZ)               // 32768
#define SMEM_TOTAL (NSTAGE * STAGE_SZ)       // 98304 (x2 CTAs = 192KB/SM)

// ---------------- scratch (device globals: allocation-free rule) ----------------
__device__ __align__(16) float g_xt[(size_t)NM * NDIN];          // tf32(x)
__device__ __align__(16) float g_wt[(size_t)NDOUT * NDIN];       // tf32(W_org)
__device__ __align__(16) float g_lxt[(size_t)NM * 32];           // tf32(lx), cols16+ = 0
__device__ __align__(16) float g_cbt[(size_t)NB * NDOUT * 32];   // tf32(comb), padded

// ---------------- PTX helpers (plain sm_80+ instructions only) ----------------
__device__ __forceinline__ uint32_t smem_u32(const void* p) {
    uint32_t a;
    asm("{ .reg .u64 t; cvta.to.shared.u64 t, %1; cvt.u32.u64 %0, t; }" : "=r"(a) : "l"(p));
    return a;
}
__device__ __forceinline__ uint32_t f2tf(float v) {
    uint32_t o;
    asm("cvt.rna.tf32.f32 %0, %1;" : "=r"(o) : "f"(v));
    return o;
}
__device__ __forceinline__ void cp16(uint32_t saddr, const void* gptr) {
    asm volatile("cp.async.cg.shared.global [%0], [%1], 16;"
                 :: "r"(saddr), "l"(__cvta_generic_to_global(gptr)) : "memory");
}
__device__ __forceinline__ void cp_commit() {
    asm volatile("cp.async.commit_group;" ::: "memory");
}
__device__ __forceinline__ void cp_wait1() {
    asm volatile("cp.async.wait_group 1;" ::: "memory");
}
#define LDSM4(r0, r1, r2, r3, addr)                                              \
    asm volatile("ldmatrix.sync.aligned.m8n8.x4.shared.b16 {%0,%1,%2,%3}, [%4];" \
                 : "=r"(r0), "=r"(r1), "=r"(r2), "=r"(r3) : "r"(addr))
#define MMATF32(c, a, b0, b1)                                                 \
    asm volatile("mma.sync.aligned.m16n8k8.row.col.f32.tf32.tf32.f32 "        \
                 "{%0,%1,%2,%3},{%4,%5,%6,%7},{%8,%9},{%0,%1,%2,%3};"         \
                 : "+f"((c)[0]), "+f"((c)[1]), "+f"((c)[2]), "+f"((c)[3])     \
                 : "r"((a)[0]), "r"((a)[1]), "r"((a)[2]), "r"((a)[3]),        \
                   "r"(b0), "r"(b1))

// 128B-row swizzle: 16B-chunk' = ch ^ (row&7); conflict-free for cp.async
// stores and 8-row ldmatrix tiles.
__device__ __forceinline__ uint32_t swof(int row, int ch) {
    return (uint32_t)(row * 128 + ((ch ^ (row & 7)) << 4));
}

// ---------------- pre-kernels: tf32 round-to-nearest conversion ----------------
__device__ __forceinline__ void cvt8(const float* src, float* dst, size_t i) {
    float4 v0 = *(const float4*)(src + i);
    float4 v1 = *(const float4*)(src + i + 4);
    uint4 o0 = make_uint4(f2tf(v0.x), f2tf(v0.y), f2tf(v0.z), f2tf(v0.w));
    uint4 o1 = make_uint4(f2tf(v1.x), f2tf(v1.y), f2tf(v1.z), f2tf(v1.w));
    *(uint4*)(dst + i) = o0;
    *(uint4*)(dst + i + 4) = o1;
}
__global__ void k_cvt_x(const float* __restrict__ x) {
    size_t i = ((size_t)blockIdx.x * 256 + threadIdx.x) * 8;
    cvt8(x, g_xt, i);
}
// blocks [0,2048): cvt W_org; [2048,2560): gate-combine -> tf32 padded
__global__ void k_cvt_w_comb(const float* __restrict__ W_org,
                             const float* __restrict__ gate,
                             const float* __restrict__ W_up) {
    if (blockIdx.x < 2048) {
        size_t i = ((size_t)blockIdx.x * 256 + threadIdx.x) * 8;
        cvt8(W_org, g_wt, i);
    } else {
        int idx = (blockIdx.x - 2048) * 256 + threadIdx.x;
        if (idx >= NB * NDOUT * NR) return;
        int b = idx / (NDOUT * NR);
        int orr = idx - b * (NDOUT * NR);
        int o = orr >> 4, r = orr & 15;
        float s = 0.f;
#pragma unroll
        for (int e = 0; e < NE; e++)
            s += __ldg(&gate[b * NE + e]) * __ldg(&W_up[(size_t)e * NDOUT * NR + orr]);
        size_t off = ((size_t)b * NDOUT + o) * 32;
        g_cbt[off + r] = __uint_as_float(f2tf(s));
        g_cbt[off + 16 + r] = 0.f;
    }
}

// ---------------- k_lx: lx[m,0:16] = x @ W_down^T via tf32 mma ----------------
#define LXW 131072                       // 16 n-rows x 2048 k x 4B (tf32 W_down)
#define LX_STG 16384                     // 128 rows x 32 k x 4B
#define LX_SMEM (LXW + 3 * LX_STG)       // 180224

__device__ __forceinline__ void lx_issue(uint32_t sb, int s, int c, int rowBase, int tid) {
    uint32_t xs = sb + LXW + s * LX_STG;
#pragma unroll
    for (int j = 0; j < 8; j++) {
        int g = tid + 128 * j;
        int row = g >> 3, ch = g & 7;
        cp16(xs + swof(row, ch), g_xt + (size_t)(rowBase + row) * NDIN + c * CK + ch * 4);
    }
}

__global__ void __launch_bounds__(128, 1) k_lx(const float* __restrict__ Wd) {
    extern __shared__ char sm[];
    const uint32_t sb = smem_u32(sm);
    const int tid = threadIdx.x;
    const int w = tid >> 5, lane = tid & 31;
    const int rowBase = blockIdx.x * 128;
    const int lane7 = lane & 7, half = (lane >> 3) & 1, kh = lane >> 4;

    // stage W_down -> tf32 smem [n][k], rows 8192B, low-3-bit chunk swizzle
    for (int idx = tid; idx < 16 * 512; idx += 128) {
        int n = idx >> 9, ch = idx & 511;
        float4 v = *(const float4*)(Wd + (size_t)n * NDIN + ch * 4);
        uint4 o = make_uint4(f2tf(v.x), f2tf(v.y), f2tf(v.z), f2tf(v.w));
        *(uint4*)(sm + n * 8192 + ((ch ^ (n & 7)) << 4)) = o;
    }

    float acc[2][2][4];
#pragma unroll
    for (int i = 0; i < 2; i++)
#pragma unroll
        for (int j = 0; j < 2; j++)
#pragma unroll
            for (int q = 0; q < 4; q++) acc[i][j][q] = 0.f;

    lx_issue(sb, 0, 0, rowBase, tid); cp_commit();
    lx_issue(sb, 1, 1, rowBase, tid); cp_commit();

    // per-lane fragment bases
    uint32_t aRow[2], aSw[2];
#pragma unroll
    for (int mt = 0; mt < 2; mt++) {
        int r = w * 32 + mt * 16 + half * 8 + lane7;
        aRow[mt] = (uint32_t)r * 128; aSw[mt] = (uint32_t)(r & 7);
    }
    const int rB = half * 8 + lane7;
    const uint32_t bOff = (uint32_t)rB * 8192, bSw = (uint32_t)(rB & 7);

    for (int c = 0; c < NCHUNK; c++) {
        cp_wait1();
        __syncthreads();
        if (c + 2 < NCHUNK) lx_issue(sb, (c + 2) % 3, c + 2, rowBase, tid);
        cp_commit();
        const uint32_t xs = sb + LXW + (c % 3) * LX_STG;
#pragma unroll
        for (int ks = 0; ks < 4; ks++) {
            uint32_t chB = (uint32_t)(((c * 4 + ks) << 1) | kh);
            uint32_t r0, r1, r2, r3;
            LDSM4(r0, r1, r2, r3, sb + bOff + ((chB ^ bSw) << 4));
            uint32_t bf0[2] = {r0, r2}, bf1[2] = {r1, r3};
#pragma unroll
            for (int mt = 0; mt < 2; mt++) {
                uint32_t a[4];
                uint32_t ch = (uint32_t)((ks << 1) | kh);
                LDSM4(a[0], a[1], a[2], a[3], xs + aRow[mt] + ((ch ^ aSw[mt]) << 4));
                MMATF32(acc[mt][0], a, bf0[0], bf0[1]);
                MMATF32(acc[mt][1], a, bf1[0], bf1[1]);
            }
        }
        __syncthreads();
    }

    // epilogue: tf32-round, store, zero-pad cols 16-31
#pragma unroll
    for (int mt = 0; mt < 2; mt++) {
        int row = rowBase + w * 32 + mt * 16 + (lane >> 2);
#pragma unroll
        for (int nt = 0; nt < 2; nt++) {
            int col = nt * 8 + (lane & 3) * 2;
            g_lxt[(size_t)row * 32 + col]           = __uint_as_float(f2tf(acc[mt][nt][0]));
            g_lxt[(size_t)row * 32 + col + 1]       = __uint_as_float(f2tf(acc[mt][nt][1]));
            g_lxt[(size_t)(row + 8) * 32 + col]     = __uint_as_float(f2tf(acc[mt][nt][2]));
            g_lxt[(size_t)(row + 8) * 32 + col + 1] = __uint_as_float(f2tf(acc[mt][nt][3]));
        }
    }
    {
        int m = rowBase + w * 32 + lane;
        uint4 z = make_uint4(0, 0, 0, 0);
        *(uint4*)&g_lxt[(size_t)m * 32 + 16] = z;
        *(uint4*)&g_lxt[(size_t)m * 32 + 24] = z;
    }
}

// ---------------- main GEMM: tf32 1-pass, 128x128 tile, 2 CTAs/SM ----------------
__device__ __forceinline__ void issue_chunk(uint32_t s, int idx,
                                            int rowBase, int colBase, int b, int tid) {
    const float *ap, *bp;
    int ld;
    if (idx < NCHUNK) {
        ap = g_xt + (size_t)rowBase * NDIN + idx * CK;
        bp = g_wt + (size_t)colBase * NDIN + idx * CK;
        ld = NDIN;
    } else {  // LoRA virtual chunk (K=16 zero-padded to 32)
        ap = g_lxt + (size_t)rowBase * 32;
        bp = g_cbt + ((size_t)b * NDOUT + colBase) * 32;
        ld = 32;
    }
#pragma unroll
    for (int j = 0; j < 4; j++) {
        int id = tid + 256 * j;
        int row = id >> 3, ch = id & 7;
        uint32_t so = swof(row, ch);
        size_t go = (size_t)row * ld + ch * 4;
        cp16(s + so, ap + go);
        cp16(s + OF_B + so, bp + go);
    }
}

__global__ void __launch_bounds__(256, 2) k_gemm(float* __restrict__ out) {
    extern __shared__ char smem[];
    const uint32_t sb0 = smem_u32(smem);
    const int tid = threadIdx.x;
    const int wid = tid >> 5, lane = tid & 31;
    const int wm = wid >> 2, wn = wid & 3;      // 2x4 warp grid, warp tile 64x32
    const int rowBase = blockIdx.y * BM;
    const int colBase = blockIdx.x * BN;
    const int b = blockIdx.y >> 5;              // NS/BM = 32 row-blocks per batch
    const int lane7 = lane & 7, half = (lane >> 3) & 1, kh = lane >> 4;

    // per-lane ldmatrix bases (tf32 fragment trick: 4 b16 8x8 tiles = m16k8)
    uint32_t aRow[4], aSw[4], bRow[2], bSw[2];
#pragma unroll
    for (int mt = 0; mt < 4; mt++) {
        int r = wm * 64 + mt * 16 + half * 8 + lane7;
        aRow[mt] = (uint32_t)r * 128; aSw[mt] = (uint32_t)(r & 7);
    }
#pragma unroll
    for (int bp = 0; bp < 2; bp++) {
        int r = wn * 32 + bp * 16 + half * 8 + lane7;
        bRow[bp] = OF_B + (uint32_t)r * 128; bSw[bp] = (uint32_t)(r & 7);
    }

    float acc[4][4][4];
#pragma unroll
    for (int i = 0; i < 4; i++)
#pragma unroll
        for (int j = 0; j < 4; j++)
#pragma unroll
            for (int q = 0; q < 4; q++) acc[i][j][q] = 0.f;

    issue_chunk(sb0 + 0 * STAGE_SZ, 0, rowBase, colBase, b, tid); cp_commit();
    issue_chunk(sb0 + 1 * STAGE_SZ, 1, rowBase, colBase, b, tid); cp_commit();

    int slot = 0, nslot = 2;
    for (int kc = 0; kc < NCHTOT; kc++) {
        cp_wait1();
        __syncthreads();
        if (kc + 2 < NCHTOT)
            issue_chunk(sb0 + nslot * STAGE_SZ, kc + 2, rowBase, colBase, b, tid);
        cp_commit();

        const uint32_t Sb = sb0 + slot * STAGE_SZ;
        slot = (slot + 1 == NSTAGE) ? 0 : slot + 1;
        nslot = (nslot + 1 == NSTAGE) ? 0 : nslot + 1;
#pragma unroll
        for (int ks = 0; ks < 4; ks++) {
            const uint32_t ch = (uint32_t)((ks << 1) | kh);
            uint32_t bf[4][2];
#pragma unroll
            for (int bp = 0; bp < 2; bp++) {
                uint32_t r0, r1, r2, r3;
                LDSM4(r0, r1, r2, r3, Sb + bRow[bp] + ((ch ^ bSw[bp]) << 4));
                bf[bp * 2 + 0][0] = r0; bf[bp * 2 + 0][1] = r2;
                bf[bp * 2 + 1][0] = r1; bf[bp * 2 + 1][1] = r3;
            }
#pragma unroll
            for (int mt = 0; mt < 4; mt++) {
                uint32_t a[4];
                LDSM4(a[0], a[1], a[2], a[3], Sb + aRow[mt] + ((ch ^ aSw[mt]) << 4));
#pragma unroll
                for (int nt = 0; nt < 4; nt++)
                    MMATF32(acc[mt][nt], a, bf[nt][0], bf[nt][1]);
            }
        }
    }

    // ---------------- epilogue ----------------
#pragma unroll
    for (int mt = 0; mt < 4; mt++) {
#pragma unroll
        for (int nt = 0; nt < 4; nt++) {
            int row = rowBase + wm * 64 + mt * 16 + (lane >> 2);
            int col = colBase + wn * 32 + nt * 8 + (lane & 3) * 2;
            *(float2*)&out[(size_t)row * NDOUT + col] =
                make_float2(acc[mt][nt][0], acc[mt][nt][1]);
            *(float2*)&out[(size_t)(row + 8) * NDOUT + col] =
                make_float2(acc[mt][nt][2], acc[mt][nt][3]);
        }
    }
}

// ---------------- launch ----------------
extern "C" void kernel_launch(void* const* d_in, const int* in_sizes, int n_in,
                              void* d_out, int out_size) {
    const float* x      = (const float*)d_in[0];
    const float* gate   = (const float*)d_in[1];
    const float* W_org  = (const float*)d_in[2];
    const float* W_down = (const float*)d_in[3];
    const float* W_up   = (const float*)d_in[4];
    float* out = (float*)d_out;

    cudaFuncSetAttribute(k_gemm, cudaFuncAttributeMaxDynamicSharedMemorySize, SMEM_TOTAL);
    cudaFuncSetAttribute(k_lx, cudaFuncAttributeMaxDynamicSharedMemorySize, LX_SMEM);

    k_cvt_x<<<(size_t)NM * NDIN / 2048, 256>>>(x);
    k_cvt_w_comb<<<2048 + 512, 256>>>(W_org, gate, W_up);
    k_lx<<<NM / 128, 128, LX_SMEM>>>(W_down);

    dim3 grid(NDOUT / BN, NM / BM);   // (16, 128) = 2048 CTAs
    k_gemm<<<grid, 256, SMEM_TOTAL>>>(out);
}